// round 15
// baseline (speedup 1.0000x reference)
#include <cuda_runtime.h>

// TriMipEncoding: x [N,3] in [0,1], fm [3,512,512,16] fp32. out [N,48].
//
// R15 = R6/R14 body (session best, 57.4us, at the calibrated L1TEX wavefront
// ceiling) with block 256 instead of 128: half the CTA count -> less CTA
// churn / shorter wave tail. Everything else untouched:
//  - unit = (point,plane,quad), c = idx&3 -> 4 lanes x 16B cover each 64B
//    texel = minimal 12 gather line-visits/point (proven vs R1/R9/R10/R11)
//  - 2 strided units/thread, 8 front-batched LDG.128
//  - evict_last keeps 50MB planes L2-resident; __stcs streams the output.

#define PLANE_H 512
#define PLANE_W 512

__device__ __forceinline__ float4 ldg_resident(const float4* p, unsigned long long pol) {
    float4 v;
    asm("ld.global.nc.L2::cache_hint.v4.f32 {%0,%1,%2,%3}, [%4], %5;"
        : "=f"(v.x), "=f"(v.y), "=f"(v.z), "=f"(v.w)
        : "l"(p), "l"(pol));
    return v;
}

struct Unit {
    const float4* a00; const float4* a01; const float4* a10; const float4* a11;
    float w00, w01, w10, w11;
};

__device__ __forceinline__ Unit decode(int idx, const float* __restrict__ x,
                                        const float4* __restrict__ fm4) {
    Unit un;
    int c = idx & 3;
    int t = idx >> 2;
    int n = t / 3;           // magic-mul
    int p = t - n * 3;

    float x0 = __ldg(x + n * 3 + 0);
    float x1 = __ldg(x + n * 3 + 1);
    float x2 = __ldg(x + n * 3 + 2);

    // plane 0: (y,z) ; plane 1: (x,z) ; plane 2: (x,y)
    float cu = (p == 0) ? x1 : x0;
    float cv = (p == 2) ? x1 : x2;

    float u = cu * (float)PLANE_W - 0.5f;
    float v = cv * (float)PLANE_H - 0.5f;
    float i0f = floorf(u);
    float j0f = floorf(v);
    float fu = u - i0f;
    float fv = v - j0f;

    int i0 = min(max((int)i0f,     0), PLANE_W - 1);
    int i1 = min(max((int)i0f + 1, 0), PLANE_W - 1);
    int j0 = min(max((int)j0f,     0), PLANE_H - 1);
    int j1 = min(max((int)j0f + 1, 0), PLANE_H - 1);

    un.w00 = (1.0f - fv) * (1.0f - fu);
    un.w01 = (1.0f - fv) * fu;
    un.w10 = fv * (1.0f - fu);
    un.w11 = fv * fu;

    size_t plane_base = (size_t)p * PLANE_H * PLANE_W * 4 + c;
    size_t r0 = plane_base + (size_t)j0 * (PLANE_W * 4);
    size_t r1 = plane_base + (size_t)j1 * (PLANE_W * 4);
    un.a00 = fm4 + r0 + (size_t)i0 * 4;
    un.a01 = fm4 + r0 + (size_t)i1 * 4;
    un.a10 = fm4 + r1 + (size_t)i0 * 4;
    un.a11 = fm4 + r1 + (size_t)i1 * 4;
    return un;
}

__device__ __forceinline__ float4 blend(const Unit& un,
                                        float4 a, float4 b, float4 d, float4 e) {
    float4 r;
    r.x = un.w00 * a.x + un.w01 * b.x + un.w10 * d.x + un.w11 * e.x;
    r.y = un.w00 * a.y + un.w01 * b.y + un.w10 * d.y + un.w11 * e.y;
    r.z = un.w00 * a.z + un.w01 * b.z + un.w10 * d.z + un.w11 * e.z;
    r.w = un.w00 * a.w + un.w01 * b.w + un.w10 * d.w + un.w11 * e.w;
    return r;
}

__global__ void __launch_bounds__(256) trimip_kernel(
    const float* __restrict__ x,
    const float4* __restrict__ fm4,
    float4* __restrict__ out4,
    int half)   // = n_pts * 6 ; unit1 = idx + half
{
    int idx = blockIdx.x * blockDim.x + threadIdx.x;
    if (idx >= half) return;

    unsigned long long pol;
    asm("createpolicy.fractional.L2::evict_last.b64 %0, 1.0;" : "=l"(pol));

    Unit u0 = decode(idx,        x, fm4);
    Unit u1 = decode(idx + half, x, fm4);

    // Front-batch all 8 gathers
    float4 a0 = ldg_resident(u0.a00, pol);
    float4 b0 = ldg_resident(u0.a01, pol);
    float4 d0 = ldg_resident(u0.a10, pol);
    float4 e0 = ldg_resident(u0.a11, pol);
    float4 a1 = ldg_resident(u1.a00, pol);
    float4 b1 = ldg_resident(u1.a01, pol);
    float4 d1 = ldg_resident(u1.a10, pol);
    float4 e1 = ldg_resident(u1.a11, pol);

    __stcs(out4 + idx,        blend(u0, a0, b0, d0, e0));
    __stcs(out4 + idx + half, blend(u1, a1, b1, d1, e1));
}

extern "C" void kernel_launch(void* const* d_in, const int* in_sizes, int n_in,
                              void* d_out, int out_size)
{
    const float*  x   = (const float*)d_in[0];    // [N,3]
    const float4* fm4 = (const float4*)d_in[1];   // [3,512,512,16] as float4
    float4* out4 = (float4*)d_out;                // [N,48] as float4

    int n_pts = in_sizes[0] / 3;
    int half = n_pts * 6;                          // n_pts*12 / 2
    int threads = 256;
    int blocks = (half + threads - 1) / threads;
    trimip_kernel<<<blocks, threads>>>(x, fm4, out4, half);
}

// round 16
// speedup vs baseline: 1.0277x; 1.0277x over previous
#include <cuda_runtime.h>

// TriMipEncoding: x [N,3] in [0,1], fm [3,512,512,16] fp32. out [N,48].
//
// FINAL (= R6/R14, session best 57.4us; block-256 variant refuted in R15).
// 4 threads per (point,plane), one float4 channel-quad each (c = idx&3 ->
// 4 lanes x 16B cover a whole 64B texel = minimal 12 gather line-visits per
// point; proven optimal vs R1/R9/R10/R11). Each thread processes 2 strided
// units with 8 front-batched LDG.128 (proven optimal vs R3/R7/R8/R12/R13).
// evict_last keeps the 50MB planes L2-resident; __stcs streams the output.
// Measured AT the calibrated L1TEX wavefront roofline:
// ~15.2 wf/point -> 41.5us busy / 0.72 pipe ceiling = 57.5us wall.

#define PLANE_H 512
#define PLANE_W 512

__device__ __forceinline__ float4 ldg_resident(const float4* p, unsigned long long pol) {
    float4 v;
    asm("ld.global.nc.L2::cache_hint.v4.f32 {%0,%1,%2,%3}, [%4], %5;"
        : "=f"(v.x), "=f"(v.y), "=f"(v.z), "=f"(v.w)
        : "l"(p), "l"(pol));
    return v;
}

struct Unit {
    const float4* a00; const float4* a01; const float4* a10; const float4* a11;
    float w00, w01, w10, w11;
};

__device__ __forceinline__ Unit decode(int idx, const float* __restrict__ x,
                                        const float4* __restrict__ fm4) {
    Unit un;
    int c = idx & 3;
    int t = idx >> 2;
    int n = t / 3;           // magic-mul
    int p = t - n * 3;

    float x0 = __ldg(x + n * 3 + 0);
    float x1 = __ldg(x + n * 3 + 1);
    float x2 = __ldg(x + n * 3 + 2);

    // plane 0: (y,z) ; plane 1: (x,z) ; plane 2: (x,y)
    float cu = (p == 0) ? x1 : x0;
    float cv = (p == 2) ? x1 : x2;

    float u = cu * (float)PLANE_W - 0.5f;
    float v = cv * (float)PLANE_H - 0.5f;
    float i0f = floorf(u);
    float j0f = floorf(v);
    float fu = u - i0f;
    float fv = v - j0f;

    int i0 = min(max((int)i0f,     0), PLANE_W - 1);
    int i1 = min(max((int)i0f + 1, 0), PLANE_W - 1);
    int j0 = min(max((int)j0f,     0), PLANE_H - 1);
    int j1 = min(max((int)j0f + 1, 0), PLANE_H - 1);

    un.w00 = (1.0f - fv) * (1.0f - fu);
    un.w01 = (1.0f - fv) * fu;
    un.w10 = fv * (1.0f - fu);
    un.w11 = fv * fu;

    size_t plane_base = (size_t)p * PLANE_H * PLANE_W * 4 + c;
    size_t r0 = plane_base + (size_t)j0 * (PLANE_W * 4);
    size_t r1 = plane_base + (size_t)j1 * (PLANE_W * 4);
    un.a00 = fm4 + r0 + (size_t)i0 * 4;
    un.a01 = fm4 + r0 + (size_t)i1 * 4;
    un.a10 = fm4 + r1 + (size_t)i0 * 4;
    un.a11 = fm4 + r1 + (size_t)i1 * 4;
    return un;
}

__device__ __forceinline__ float4 blend(const Unit& un,
                                        float4 a, float4 b, float4 d, float4 e) {
    float4 r;
    r.x = un.w00 * a.x + un.w01 * b.x + un.w10 * d.x + un.w11 * e.x;
    r.y = un.w00 * a.y + un.w01 * b.y + un.w10 * d.y + un.w11 * e.y;
    r.z = un.w00 * a.z + un.w01 * b.z + un.w10 * d.z + un.w11 * e.z;
    r.w = un.w00 * a.w + un.w01 * b.w + un.w10 * d.w + un.w11 * e.w;
    return r;
}

__global__ void __launch_bounds__(128) trimip_kernel(
    const float* __restrict__ x,
    const float4* __restrict__ fm4,
    float4* __restrict__ out4,
    int half)   // = n_pts * 6 ; unit1 = idx + half
{
    int idx = blockIdx.x * blockDim.x + threadIdx.x;
    if (idx >= half) return;

    unsigned long long pol;
    asm("createpolicy.fractional.L2::evict_last.b64 %0, 1.0;" : "=l"(pol));

    Unit u0 = decode(idx,        x, fm4);
    Unit u1 = decode(idx + half, x, fm4);

    // Front-batch all 8 gathers
    float4 a0 = ldg_resident(u0.a00, pol);
    float4 b0 = ldg_resident(u0.a01, pol);
    float4 d0 = ldg_resident(u0.a10, pol);
    float4 e0 = ldg_resident(u0.a11, pol);
    float4 a1 = ldg_resident(u1.a00, pol);
    float4 b1 = ldg_resident(u1.a01, pol);
    float4 d1 = ldg_resident(u1.a10, pol);
    float4 e1 = ldg_resident(u1.a11, pol);

    __stcs(out4 + idx,        blend(u0, a0, b0, d0, e0));
    __stcs(out4 + idx + half, blend(u1, a1, b1, d1, e1));
}

extern "C" void kernel_launch(void* const* d_in, const int* in_sizes, int n_in,
                              void* d_out, int out_size)
{
    const float*  x   = (const float*)d_in[0];    // [N,3]
    const float4* fm4 = (const float4*)d_in[1];   // [3,512,512,16] as float4
    float4* out4 = (float4*)d_out;                // [N,48] as float4

    int n_pts = in_sizes[0] / 3;
    int half = n_pts * 6;                          // n_pts*12 / 2
    int threads = 128;
    int blocks = (half + threads - 1) / threads;
    trimip_kernel<<<blocks, threads>>>(x, fm4, out4, half);
}

// round 17
// speedup vs baseline: 1.0340x; 1.0061x over previous
#include <cuda_runtime.h>

// TriMipEncoding: x [N,3] in [0,1], fm [3,512,512,16] fp32. out [N,48].
//
// R17 = R14 body (session best 57.4us, at the calibrated L1TEX wavefront
// roofline) with block 64: R15 established 128 > 256 (finer CTA granularity
// -> better L1 util); this probes one step further down. Everything else is
// the proven optimum:
//  - unit = (point,plane,quad), c = idx&3 -> 4 lanes x 16B per 64B texel
//    = minimal 12 gather line-visits/point
//  - 2 strided units/thread, 8 front-batched LDG.128
//  - evict_last keeps 50MB planes L2-resident; __stcs streams output.

#define PLANE_H 512
#define PLANE_W 512

__device__ __forceinline__ float4 ldg_resident(const float4* p, unsigned long long pol) {
    float4 v;
    asm("ld.global.nc.L2::cache_hint.v4.f32 {%0,%1,%2,%3}, [%4], %5;"
        : "=f"(v.x), "=f"(v.y), "=f"(v.z), "=f"(v.w)
        : "l"(p), "l"(pol));
    return v;
}

struct Unit {
    const float4* a00; const float4* a01; const float4* a10; const float4* a11;
    float w00, w01, w10, w11;
};

__device__ __forceinline__ Unit decode(int idx, const float* __restrict__ x,
                                        const float4* __restrict__ fm4) {
    Unit un;
    int c = idx & 3;
    int t = idx >> 2;
    int n = t / 3;           // magic-mul
    int p = t - n * 3;

    float x0 = __ldg(x + n * 3 + 0);
    float x1 = __ldg(x + n * 3 + 1);
    float x2 = __ldg(x + n * 3 + 2);

    // plane 0: (y,z) ; plane 1: (x,z) ; plane 2: (x,y)
    float cu = (p == 0) ? x1 : x0;
    float cv = (p == 2) ? x1 : x2;

    float u = cu * (float)PLANE_W - 0.5f;
    float v = cv * (float)PLANE_H - 0.5f;
    float i0f = floorf(u);
    float j0f = floorf(v);
    float fu = u - i0f;
    float fv = v - j0f;

    int i0 = min(max((int)i0f,     0), PLANE_W - 1);
    int i1 = min(max((int)i0f + 1, 0), PLANE_W - 1);
    int j0 = min(max((int)j0f,     0), PLANE_H - 1);
    int j1 = min(max((int)j0f + 1, 0), PLANE_H - 1);

    un.w00 = (1.0f - fv) * (1.0f - fu);
    un.w01 = (1.0f - fv) * fu;
    un.w10 = fv * (1.0f - fu);
    un.w11 = fv * fu;

    size_t plane_base = (size_t)p * PLANE_H * PLANE_W * 4 + c;
    size_t r0 = plane_base + (size_t)j0 * (PLANE_W * 4);
    size_t r1 = plane_base + (size_t)j1 * (PLANE_W * 4);
    un.a00 = fm4 + r0 + (size_t)i0 * 4;
    un.a01 = fm4 + r0 + (size_t)i1 * 4;
    un.a10 = fm4 + r1 + (size_t)i0 * 4;
    un.a11 = fm4 + r1 + (size_t)i1 * 4;
    return un;
}

__device__ __forceinline__ float4 blend(const Unit& un,
                                        float4 a, float4 b, float4 d, float4 e) {
    float4 r;
    r.x = un.w00 * a.x + un.w01 * b.x + un.w10 * d.x + un.w11 * e.x;
    r.y = un.w00 * a.y + un.w01 * b.y + un.w10 * d.y + un.w11 * e.y;
    r.z = un.w00 * a.z + un.w01 * b.z + un.w10 * d.z + un.w11 * e.z;
    r.w = un.w00 * a.w + un.w01 * b.w + un.w10 * d.w + un.w11 * e.w;
    return r;
}

__global__ void __launch_bounds__(64) trimip_kernel(
    const float* __restrict__ x,
    const float4* __restrict__ fm4,
    float4* __restrict__ out4,
    int half)   // = n_pts * 6 ; unit1 = idx + half
{
    int idx = blockIdx.x * blockDim.x + threadIdx.x;
    if (idx >= half) return;

    unsigned long long pol;
    asm("createpolicy.fractional.L2::evict_last.b64 %0, 1.0;" : "=l"(pol));

    Unit u0 = decode(idx,        x, fm4);
    Unit u1 = decode(idx + half, x, fm4);

    // Front-batch all 8 gathers
    float4 a0 = ldg_resident(u0.a00, pol);
    float4 b0 = ldg_resident(u0.a01, pol);
    float4 d0 = ldg_resident(u0.a10, pol);
    float4 e0 = ldg_resident(u0.a11, pol);
    float4 a1 = ldg_resident(u1.a00, pol);
    float4 b1 = ldg_resident(u1.a01, pol);
    float4 d1 = ldg_resident(u1.a10, pol);
    float4 e1 = ldg_resident(u1.a11, pol);

    __stcs(out4 + idx,        blend(u0, a0, b0, d0, e0));
    __stcs(out4 + idx + half, blend(u1, a1, b1, d1, e1));
}

extern "C" void kernel_launch(void* const* d_in, const int* in_sizes, int n_in,
                              void* d_out, int out_size)
{
    const float*  x   = (const float*)d_in[0];    // [N,3]
    const float4* fm4 = (const float4*)d_in[1];   // [3,512,512,16] as float4
    float4* out4 = (float4*)d_out;                // [N,48] as float4

    int n_pts = in_sizes[0] / 3;
    int half = n_pts * 6;                          // n_pts*12 / 2
    int threads = 64;
    int blocks = (half + threads - 1) / threads;
    trimip_kernel<<<blocks, threads>>>(x, fm4, out4, half);
}